// round 2
// baseline (speedup 1.0000x reference)
#include <cuda_runtime.h>

#define W 512
#define NB 16
#define NPIX (W * W)
#define NTOT (NB * NPIX)
#define CELL_W (200.0f / 512.0f)

// Scratch state (allowed: __device__ globals, not cudaMalloc)
__device__ float g_terrA[NTOT];
__device__ float g_terrB[NTOT];
__device__ float g_sed[NTOT];
__device__ float g_wat[NTOT];
__device__ float g_vel[NTOT];

template <bool FIRST>
__device__ __forceinline__ float loadT(const float* __restrict__ t, int b, int i, int j) {
    float v = __ldg(&t[b * NPIX + i * W + j]);
    if (FIRST) v = (1.0f - v) * 0.5f;  // fused input transform (1 - x) / 2
    return v;
}

template <bool FIRST>
__device__ __forceinline__ float gatherT(const float* __restrict__ t, int b, int ix, int iy) {
    // reference: read (t - 1) with OOB -> 0
    if (ix < 0 || ix > W - 1 || iy < 0 || iy > W - 1) return 0.0f;
    return loadT<FIRST>(t, b, iy, ix) - 1.0f;
}

template <bool FIRST, bool LAST>
__global__ __launch_bounds__(256) void erosion_step(
    const float* __restrict__ ext_in,   // input_terrain (only used when FIRST)
    float* __restrict__ final_out,      // d_out (only used when LAST)
    const float* __restrict__ rain,     // this iteration's (W,W) rainfall slice
    const float* __restrict__ gnoise,   // this iteration's (W,W) gradient-noise slice
    int parity,                         // it & 1 : selects ping-pong direction
    const float* __restrict__ s_rain_rate,
    const float* __restrict__ s_evap,
    const float* __restrict__ s_mhd,
    const float* __restrict__ s_heps,
    const float* __restrict__ s_grav,
    const float* __restrict__ s_ks,
    const float* __restrict__ s_diss,
    const float* __restrict__ s_dep)
{
    const int j = blockIdx.x * 32 + threadIdx.x;
    const int i = blockIdx.y * 8 + threadIdx.y;
    const int b = blockIdx.z;
    const int idx = b * NPIX + i * W + j;

    const float* tin = FIRST ? ext_in : (parity ? g_terrA : g_terrB);
    float* tout = parity ? g_terrB : g_terrA;

    // carried state
    float sed, wat, vel;
    if (FIRST) { sed = 0.0f; wat = 0.0f; vel = 0.0f; }
    else       { sed = g_sed[idx]; wat = g_wat[idx]; vel = g_vel[idx]; }

    // scalars
    const float rainr = fmaxf(__ldg(s_rain_rate), 0.0f);
    const float evapr = fmaxf(__ldg(s_evap), 0.0f);
    const float mhd   = __ldg(s_mhd);
    const float heps  = __ldg(s_heps);
    const float gravr = fmaxf(__ldg(s_grav), 0.0f);
    const float ksr   = fmaxf(__ldg(s_ks), 0.0f);
    const float dissr = __ldg(s_diss);
    const float depr  = __ldg(s_dep);

    // water = water + relu(rain_rate) * rain
    wat += rainr * __ldg(&rain[i * W + j]);

    // ---- simple_gradient ----
    const float tc = loadT<FIRST>(tin, b, i, j);
    float dx, dy;
    if (i == 0)          dx = 0.5f * (tc * 1.1f - tc);
    else if (i == W - 1) dx = 0.5f * (tc * 0.9f - tc);
    else                 dx = 0.5f * (loadT<FIRST>(tin, b, i + 1, j) - loadT<FIRST>(tin, b, i - 1, j));
    if (j == 0)          dy = 0.5f * (tc * 1.1f - tc);
    else if (j == W - 1) dy = 0.5f * (tc * 0.9f - tc);
    else                 dy = 0.5f * (loadT<FIRST>(tin, b, i, j + 1) - loadT<FIRST>(tin, b, i, j - 1));

    const float mag = sqrtf(dx * dx + dy * dy + 1e-11f);
    const float rX = __ldg(&gnoise[i * W + j]);
    const float rY = sqrtf(1.0f - rX * rX);
    const float factor = fmaxf(1e-10f - mag, 0.0f);
    const float fdx = (dx + factor * rX) / (mag + factor);
    const float fdy = (dy + factor * rY) / (mag + factor);

    // ---- bilinear_sample(terrain, -gradient) ----
    const float fx = (float)j - fdx;
    const float fy = (float)i - fdy;
    const float x0f = floorf(fx);
    const float y0f = floorf(fy);
    const float wx1 = fx - x0f;
    const float wy1 = fy - y0f;
    const int x0 = (int)x0f;
    const int y0 = (int)y0f;

    const float g00 = gatherT<FIRST>(tin, b, x0,     y0);
    const float g10 = gatherT<FIRST>(tin, b, x0 + 1, y0);
    const float g01 = gatherT<FIRST>(tin, b, x0,     y0 + 1);
    const float g11 = gatherT<FIRST>(tin, b, x0 + 1, y0 + 1);
    const float neighbor =
        (1.0f - wy1) * ((1.0f - wx1) * g00 + wx1 * g10) +
        wy1 * ((1.0f - wx1) * g01 + wx1 * g11) + 1.0f;

    // ---- erosion/deposition ----
    const float hd = tc - neighbor;
    const float hds = (hd - heps > 0.0f) ? 1.0f : 0.0f;        // sign(relu(hd - eps))
    const float nhd = hds * fmaxf(hd, mhd);
    const float sed_cap = nhd / CELL_W * vel * wat * ksr;
    const float ftb = (hd < 0.0f) ? 1.0f : 0.0f;               // relu(sign(-hd))
    const float fst = fminf(fmaxf(-hd, 0.0f), sed);
    const float sdiff = sed - sed_cap;
    const float third = (1.0f - ftb) *
        (fmaxf(sdiff * depr, 0.0f) - fmaxf(-sdiff * dissr, 0.0f));
    const float dep = fmaxf(-fmaxf(hd, 0.0f), fst + third);
    sed = sed - dep;
    const float tn = tc + dep;

    // ---- displace(a, gradient): pointwise rescale with column-edge masks ----
    const float w2 = fmaxf(1.0f - fabsf(fdy), 0.0f);
    const float e1 = (j == W - 1) ? 0.0f : fmaxf(-fdy, 0.0f);
    const float e3 = (j == 0)     ? 0.0f : fmaxf(fdy, 0.0f);
    sed = e1 * sed + w2 * sed + e3 * sed;
    wat = e1 * wat + w2 * wat + e3 * wat;

    vel = gravr * hd / CELL_W;
    wat = wat * (1.0f - evapr);

    if (LAST) {
        // fused output transform: relu(1 + (1 - 2t)) - 1
        final_out[idx] = fmaxf(1.0f + (1.0f - tn * 2.0f), 0.0f) - 1.0f;
    } else {
        tout[idx] = tn;
        g_sed[idx] = sed;
        g_wat[idx] = wat;
        g_vel[idx] = vel;
    }
}

extern "C" void kernel_launch(void* const* d_in, const int* in_sizes, int n_in,
                              void* d_out, int out_size)
{
    const float* input_terrain = (const float*)d_in[0];
    const float* rainfall      = (const float*)d_in[1];  // (10, 512, 512)
    const float* gradnoise     = (const float*)d_in[2];  // (10, 512, 512)
    const float* s_rain_rate   = (const float*)d_in[3];
    const float* s_evap        = (const float*)d_in[4];
    const float* s_mhd         = (const float*)d_in[5];
    const float* s_heps        = (const float*)d_in[6];
    const float* s_grav        = (const float*)d_in[7];
    const float* s_ks          = (const float*)d_in[8];
    const float* s_diss        = (const float*)d_in[9];
    const float* s_dep         = (const float*)d_in[10];
    float* out = (float*)d_out;

    dim3 blk(32, 8, 1);
    dim3 grd(W / 32, W / 8, NB);

    for (int it = 0; it < 10; ++it) {
        const float* rain = rainfall + it * NPIX;
        const float* gn   = gradnoise + it * NPIX;
        const int parity = it & 1;
        if (it == 0) {
            erosion_step<true, false><<<grd, blk>>>(
                input_terrain, out, rain, gn, parity,
                s_rain_rate, s_evap, s_mhd, s_heps, s_grav, s_ks, s_diss, s_dep);
        } else if (it == 9) {
            erosion_step<false, true><<<grd, blk>>>(
                input_terrain, out, rain, gn, parity,
                s_rain_rate, s_evap, s_mhd, s_heps, s_grav, s_ks, s_diss, s_dep);
        } else {
            erosion_step<false, false><<<grd, blk>>>(
                input_terrain, out, rain, gn, parity,
                s_rain_rate, s_evap, s_mhd, s_heps, s_grav, s_ks, s_diss, s_dep);
        }
    }
}